// round 2
// baseline (speedup 1.0000x reference)
#include <cuda_runtime.h>
#include <math.h>

#define TS   64
#define BB   32
#define VV   32000
#define HH   1024
#define EMBD 512
#define KX   1536          // EMB + H
#define G4   4096          // 4*H

// ---------------- device scratch (no allocations allowed) ----------------
// packed layout for GEMV activations: elem(k,b) at ((k>>2)*BB + b)*4 + (k&3)
__device__ __align__(16) float d_x4[KX * BB];        // [emb(512) | feed/comb(1024)] packed
__device__ __align__(16) float d_hp0[HH * BB];       // h layer0, packed
__device__ __align__(16) float d_hp1[HH * BB];       // h layer1, packed
__device__ float d_h1pl[HH * BB];                    // h layer1, planar [h][b]
__device__ float d_c0s[HH * BB];                     // c layer0, planar
__device__ float d_c1s[HH * BB];                     // c layer1, planar
__device__ float d_g[G4 * BB];                       // gate pre-activations, planar [j][b]
__device__ float d_hbuf[(size_t)TS * HH * BB];       // planar per step
__device__ float d_keys[(size_t)TS * HH * BB];       // planar per step
__device__ float d_sc[TS * BB];
__device__ float d_dist[TS * BB];
__device__ __align__(16) float d_sum4[HH * BB];      // summary, packed
__device__ float d_logits[(size_t)VV * BB];          // planar [v][b]
__device__ float d_pmax[BB];
__device__ float d_psum[BB];

__device__ __forceinline__ float sigm(float x) { return 1.f / (1.f + expf(-x)); }

// ---------------- GEMV: out[j][b] = sum_k A1[j][k]*X1[k][b] + sum_k A2[j][k]*X2[k][b] + bias
// X is packed-float4 over k. 2 warps/block, 8 rows/warp -> 16 rows/block. lane = batch.
__global__ void __launch_bounds__(64) k_gemv(
    const float* __restrict__ A1, int K1, int lda1, const float* __restrict__ X1,
    const float* __restrict__ A2, int K2, int lda2, const float* __restrict__ X2,
    const float* __restrict__ bias1, const float* __restrict__ bias2,
    float* __restrict__ out, int out_packed, int out_row_off)
{
    const int lane = threadIdx.x & 31;
    const int warp = threadIdx.x >> 5;
    const int j0 = (blockIdx.x * 2 + warp) * 8;

    float acc[8];
#pragma unroll
    for (int r = 0; r < 8; r++) acc[r] = 0.f;

    {
        const float4* Xv = (const float4*)X1;
        const float* ab = A1 + (size_t)j0 * lda1;
        for (int k = 0; k < K1; k += 4) {
            float4 xv = Xv[(k >> 2) * BB + lane];
#pragma unroll
            for (int r = 0; r < 8; r++) {
                float4 w = *(const float4*)(ab + (size_t)r * lda1 + k);
                acc[r] = fmaf(w.x, xv.x, acc[r]);
                acc[r] = fmaf(w.y, xv.y, acc[r]);
                acc[r] = fmaf(w.z, xv.z, acc[r]);
                acc[r] = fmaf(w.w, xv.w, acc[r]);
            }
        }
    }
    if (A2) {
        const float4* Xv = (const float4*)X2;
        const float* ab = A2 + (size_t)j0 * lda2;
        for (int k = 0; k < K2; k += 4) {
            float4 xv = Xv[(k >> 2) * BB + lane];
#pragma unroll
            for (int r = 0; r < 8; r++) {
                float4 w = *(const float4*)(ab + (size_t)r * lda2 + k);
                acc[r] = fmaf(w.x, xv.x, acc[r]);
                acc[r] = fmaf(w.y, xv.y, acc[r]);
                acc[r] = fmaf(w.z, xv.z, acc[r]);
                acc[r] = fmaf(w.w, xv.w, acc[r]);
            }
        }
    }
#pragma unroll
    for (int r = 0; r < 8; r++) {
        int j = j0 + r;
        float v = acc[r];
        if (bias1) v += bias1[j];
        if (bias2) v += bias2[j];
        if (out_packed) {
            int jj = j + out_row_off;
            out[((jj >> 2) * BB + lane) * 4 + (jj & 3)] = v;
        } else {
            out[(size_t)j * BB + lane] = v;
        }
    }
}

// ---------------- LSTM gate nonlinearity ----------------
__global__ void k_gates(const float* __restrict__ g, float* __restrict__ c,
                        float* __restrict__ hp, float* __restrict__ hpl,
                        float* __restrict__ hbuf)
{
    int i = blockIdx.x * blockDim.x + threadIdx.x;   // over H*B, i = h*32+b
    int h = i >> 5, b = i & 31;
    float ig = g[i];
    float fg = g[HH * BB + i];
    float gg = g[2 * HH * BB + i];
    float og = g[3 * HH * BB + i];
    float cc = c[i];
    float c2 = sigm(fg) * cc + sigm(ig) * tanhf(gg);
    float h2 = sigm(og) * tanhf(c2);
    c[i] = c2;
    hp[((h >> 2) * BB + b) * 4 + (h & 3)] = h2;
    if (hpl)  hpl[i]  = h2;
    if (hbuf) hbuf[i] = h2;
}

// ---------------- init: transpose h0/c0, zero feed region ----------------
__global__ void k_init(const float* __restrict__ h0, const float* __restrict__ c0,
                       float* hp0, float* hp1, float* h1pl, float* c0d, float* c1d, float* x4)
{
    int i = blockIdx.x * blockDim.x + threadIdx.x;   // over H*B
    if (i >= HH * BB) return;
    int h = i >> 5, b = i & 31;
    float v0 = h0[(size_t)b * HH + h];
    float v1 = h0[(size_t)BB * HH + (size_t)b * HH + h];
    int p = ((h >> 2) * BB + b) * 4 + (h & 3);
    hp0[p] = v0;
    hp1[p] = v1;
    h1pl[i] = v1;
    c0d[i] = c0[(size_t)b * HH + h];
    c1d[i] = c0[(size_t)BB * HH + (size_t)b * HH + h];
    x4[EMBD * BB + i] = 0.f;                         // feed=0 at t=0
}

// ---------------- embedding gather into packed x ----------------
__global__ void k_embed(const float* __restrict__ E, const int* __restrict__ toks, int t,
                        float* __restrict__ x4)
{
    int i = blockIdx.x * blockDim.x + threadIdx.x;   // over EMB*B (packed index)
    int b = (i >> 2) & 31;
    int k = (i >> 7) * 4 + (i & 3);
    int tok = toks[t * BB + b];
    x4[i] = E[(size_t)tok * EMBD + k];
}

// ---------------- attention scores: sc[s][b] = key[s][b].htop[b] + pad penalty ----
__global__ void k_scores(const float* __restrict__ keys, const float* __restrict__ htop,
                         const int* __restrict__ toks, float* __restrict__ sc)
{
    int s = blockIdx.x;
    int lane = threadIdx.x & 31, warp = threadIdx.x >> 5;   // 256 threads, 8 warps
    const float* ks = keys + (size_t)s * HH * BB;
    float acc = 0.f;
    for (int h = warp; h < HH; h += 8)
        acc = fmaf(ks[h * BB + lane], htop[h * BB + lane], acc);
    __shared__ float red[8][BB];
    red[warp][lane] = acc;
    __syncthreads();
    if (warp == 0) {
        float v = 0.f;
#pragma unroll
        for (int r = 0; r < 8; r++) v += red[r][lane];
        if (toks[s * BB + lane] == 0) v -= 99999.f;   // PAD mask
        sc[s * BB + lane] = v;
    }
}

// ---------------- softmax over s<=t (per batch) ----------------
__global__ void k_softmax(const float* __restrict__ sc, float* __restrict__ dist, int t)
{
    int b = threadIdx.x;                              // 32 threads
    float m = -1e30f;
    for (int s = 0; s <= t; s++) m = fmaxf(m, sc[s * BB + b]);
    float sum = 0.f;
    for (int s = 0; s <= t; s++) sum += expf(sc[s * BB + b] - m);
    float inv = 1.f / sum;
    for (int s = 0; s <= t; s++) dist[s * BB + b] = expf(sc[s * BB + b] - m) * inv;
}

// ---------------- summary[h][b] = sum_s dist[s][b]*hbuf[s][h][b] (packed out) ----
__global__ void k_summary(const float* __restrict__ dist, const float* __restrict__ hbuf,
                          int t, float* __restrict__ sum4)
{
    int i = blockIdx.x * blockDim.x + threadIdx.x;   // over H*B, planar
    int b = i & 31, h = i >> 5;
    float acc = 0.f;
    for (int s = 0; s <= t; s++)
        acc = fmaf(dist[s * BB + b], hbuf[(size_t)s * HH * BB + i], acc);
    sum4[((h >> 2) * BB + b) * 4 + (h & 3)] = acc;
}

// ---------------- per-batch max & sum(exp) over logits ----------------
__global__ void k_reduce(const float* __restrict__ logits, float* pmax, float* psum)
{
    int b = blockIdx.x;
    int tid = threadIdx.x;                            // 256
    __shared__ float sm[256];
    float m = -1e30f;
    for (int v = tid; v < VV; v += 256) m = fmaxf(m, logits[(size_t)v * BB + b]);
    sm[tid] = m; __syncthreads();
    for (int w = 128; w > 0; w >>= 1) { if (tid < w) sm[tid] = fmaxf(sm[tid], sm[tid + w]); __syncthreads(); }
    float bm = sm[0]; __syncthreads();
    float s = 0.f;
    for (int v = tid; v < VV; v += 256) s += expf(logits[(size_t)v * BB + b] - bm);
    sm[tid] = s; __syncthreads();
    for (int w = 128; w > 0; w >>= 1) { if (tid < w) sm[tid] += sm[tid + w]; __syncthreads(); }
    if (tid == 0) { pmax[b] = bm; psum[b] = sm[0]; }
}

// ---------------- default output: log(cw*EPS + (1-cw)*p[v]) ----------------
__global__ void k_out(const float* __restrict__ logits, const float* __restrict__ pmax,
                      const float* __restrict__ psum, float* __restrict__ out, int t)
{
    int i = blockIdx.x * blockDim.x + threadIdx.x;
    if (i >= BB * VV) return;
    int b = i / VV, v = i - b * VV;
    float m = pmax[b], inv = 1.f / psum[b];
    float pv = expf(logits[(size_t)v * BB + b] - m) * inv;
    float cw = expf(logits[3 * BB + b] - m) * inv;
    out[(size_t)(t * BB + b) * VV + v] = logf(cw * 1e-7f + (1.f - cw) * pv);
}

// ---------------- fixup scattered copy-prob entries (duplicate-aware, no atomics) ----
__global__ void k_fixup(const int* __restrict__ toks, const float* __restrict__ dist,
                        const float* __restrict__ logits, const float* __restrict__ pmax,
                        const float* __restrict__ psum, float* __restrict__ out, int t)
{
    int s = blockIdx.x, b = threadIdx.x;              // (t+1) blocks x 32
    int v = toks[s * BB + b];
    for (int sp = 0; sp < s; sp++)
        if (toks[sp * BB + b] == v) return;           // only first occurrence writes
    float S = 0.f;
    for (int sp = s; sp <= t; sp++)
        if (toks[sp * BB + b] == v) S += dist[sp * BB + b];
    float m = pmax[b], inv = 1.f / psum[b];
    float pv = expf(logits[(size_t)v * BB + b] - m) * inv;
    float cw = expf(logits[3 * BB + b] - m) * inv;
    out[(size_t)(t * BB + b) * VV + v] = logf(cw * (1e-7f + S) + (1.f - cw) * pv);
}

// ---------------- host launch ----------------
extern "C" void kernel_launch(void* const* d_in, const int* in_sizes, int n_in,
                              void* d_out, int out_size)
{
    const int*   toks = (const int*)d_in[0];
    const float* h0   = (const float*)d_in[1];
    const float* c0   = (const float*)d_in[2];
    const float* E    = (const float*)d_in[3];
    const float* Wih0 = (const float*)d_in[4];
    const float* Whh0 = (const float*)d_in[5];
    const float* bih0 = (const float*)d_in[6];
    const float* bhh0 = (const float*)d_in[7];
    const float* Wih1 = (const float*)d_in[8];
    const float* Whh1 = (const float*)d_in[9];
    const float* bih1 = (const float*)d_in[10];
    const float* bhh1 = (const float*)d_in[11];
    const float* Wk   = (const float*)d_in[12];
    const float* bk   = (const float*)d_in[13];
    const float* Wc   = (const float*)d_in[14];
    const float* bc   = (const float*)d_in[15];
    const float* Wp   = (const float*)d_in[16];
    const float* bp   = (const float*)d_in[17];
    float* out = (float*)d_out;

    float *x4, *hp0, *hp1, *h1pl, *c0d, *c1d, *g, *hbuf, *keys, *sc, *dist, *sum4, *logits, *pmax, *psum;
    cudaGetSymbolAddress((void**)&x4,     d_x4);
    cudaGetSymbolAddress((void**)&hp0,    d_hp0);
    cudaGetSymbolAddress((void**)&hp1,    d_hp1);
    cudaGetSymbolAddress((void**)&h1pl,   d_h1pl);
    cudaGetSymbolAddress((void**)&c0d,    d_c0s);
    cudaGetSymbolAddress((void**)&c1d,    d_c1s);
    cudaGetSymbolAddress((void**)&g,      d_g);
    cudaGetSymbolAddress((void**)&hbuf,   d_hbuf);
    cudaGetSymbolAddress((void**)&keys,   d_keys);
    cudaGetSymbolAddress((void**)&sc,     d_sc);
    cudaGetSymbolAddress((void**)&dist,   d_dist);
    cudaGetSymbolAddress((void**)&sum4,   d_sum4);
    cudaGetSymbolAddress((void**)&logits, d_logits);
    cudaGetSymbolAddress((void**)&pmax,   d_pmax);
    cudaGetSymbolAddress((void**)&psum,   d_psum);

    k_init<<<(HH * BB + 255) / 256, 256>>>(h0, c0, hp0, hp1, h1pl, c0d, c1d, x4);

    for (int t = 0; t < TS; t++) {
        k_embed<<<(EMBD * BB) / 256, 256>>>(E, toks, t, x4);
        // LSTM layer 0: g = Wih0.x + Whh0.h0 + biases
        k_gemv<<<G4 / 16, 64>>>(Wih0, KX, KX, x4, Whh0, HH, HH, hp0, bih0, bhh0, g, 0, 0);
        k_gates<<<(HH * BB) / 256, 256>>>(g, c0d, hp0, nullptr, nullptr);
        // LSTM layer 1
        k_gemv<<<G4 / 16, 64>>>(Wih1, HH, HH, hp0, Whh1, HH, HH, hp1, bih1, bhh1, g, 0, 0);
        k_gates<<<(HH * BB) / 256, 256>>>(g, c1d, hp1, h1pl, hbuf + (size_t)t * HH * BB);
        // key[t] = Wk.htop + bk
        k_gemv<<<HH / 16, 64>>>(Wk, HH, HH, hp1, nullptr, 0, 0, nullptr, bk, nullptr,
                                keys + (size_t)t * HH * BB, 0, 0);
        k_scores<<<t + 1, 256>>>(keys, h1pl, toks, sc);
        k_softmax<<<1, 32>>>(sc, dist, t);
        k_summary<<<(HH * BB) / 256, 256>>>(dist, hbuf, t, sum4);
        // comb = Wc.[htop; summary] + bc  -> written packed into feed region of x4
        k_gemv<<<HH / 16, 64>>>(Wc, HH, 2 * HH, hp1, Wc + HH, HH, 2 * HH, sum4, bc, nullptr,
                                x4, 1, EMBD);
        // logits = Wp.comb + bp
        k_gemv<<<VV / 16, 64>>>(Wp, HH, HH, x4 + EMBD * BB, nullptr, 0, 0, nullptr, bp, nullptr,
                                logits, 0, 0);
        k_reduce<<<BB, 256>>>(logits, pmax, psum);
        k_out<<<(BB * VV + 255) / 256, 256>>>(logits, pmax, psum, out, t);
        k_fixup<<<t + 1, BB>>>(toks, dist, logits, pmax, psum, out, t);
    }
}

// round 3
// speedup vs baseline: 1.0013x; 1.0013x over previous
#include <cuda_runtime.h>
#include <math.h>

#define TS   64
#define BB   32
#define VV   32000
#define HH   1024
#define EMBD 512
#define KX   1536          // EMB + H
#define G4   4096          // 4*H

// ---------------- device scratch (no allocations allowed) ----------------
// packed layout for GEMV activations: elem(k,b) at ((k>>2)*BB + b)*4 + (k&3)
__device__ __align__(16) float d_x4[KX * BB];        // [emb(512) | feed/comb(1024)] packed
__device__ __align__(16) float d_hp0[HH * BB];       // h layer0, packed
__device__ __align__(16) float d_hp1[HH * BB];       // h layer1, packed
__device__ float d_h1pl[HH * BB];                    // h layer1, planar [h][b]
__device__ float d_c0s[HH * BB];                     // c layer0, planar
__device__ float d_c1s[HH * BB];                     // c layer1, planar
__device__ float d_g[G4 * BB];                       // gate pre-activations, planar [j][b]
__device__ float d_hbuf[(size_t)TS * HH * BB];       // planar per step
__device__ float d_keys[(size_t)TS * HH * BB];       // planar per step
__device__ float d_sc[TS * BB];
__device__ float d_dist[TS * BB];
__device__ __align__(16) float d_sum4[HH * BB];      // summary, packed
__device__ float d_logits[(size_t)VV * BB];          // planar [v][b]
__device__ float d_pmax[BB];
__device__ float d_psum[BB];

__device__ __forceinline__ float sigm(float x) { return 1.f / (1.f + expf(-x)); }

// ---------------- GEMV: out[j][b] = sum_k A1[j][k]*X1[k][b] + sum_k A2[j][k]*X2[k][b] + bias
// X is packed-float4 over k. 2 warps/block, 8 rows/warp -> 16 rows/block. lane = batch.
__global__ void __launch_bounds__(64) k_gemv(
    const float* __restrict__ A1, int K1, int lda1, const float* __restrict__ X1,
    const float* __restrict__ A2, int K2, int lda2, const float* __restrict__ X2,
    const float* __restrict__ bias1, const float* __restrict__ bias2,
    float* __restrict__ out, int out_packed, int out_row_off)
{
    const int lane = threadIdx.x & 31;
    const int warp = threadIdx.x >> 5;
    const int j0 = (blockIdx.x * 2 + warp) * 8;

    float acc[8];
#pragma unroll
    for (int r = 0; r < 8; r++) acc[r] = 0.f;

    {
        const float4* Xv = (const float4*)X1;
        const float* ab = A1 + (size_t)j0 * lda1;
        for (int k = 0; k < K1; k += 4) {
            float4 xv = Xv[(k >> 2) * BB + lane];
#pragma unroll
            for (int r = 0; r < 8; r++) {
                float4 w = *(const float4*)(ab + (size_t)r * lda1 + k);
                acc[r] = fmaf(w.x, xv.x, acc[r]);
                acc[r] = fmaf(w.y, xv.y, acc[r]);
                acc[r] = fmaf(w.z, xv.z, acc[r]);
                acc[r] = fmaf(w.w, xv.w, acc[r]);
            }
        }
    }
    if (A2) {
        const float4* Xv = (const float4*)X2;
        const float* ab = A2 + (size_t)j0 * lda2;
        for (int k = 0; k < K2; k += 4) {
            float4 xv = Xv[(k >> 2) * BB + lane];
#pragma unroll
            for (int r = 0; r < 8; r++) {
                float4 w = *(const float4*)(ab + (size_t)r * lda2 + k);
                acc[r] = fmaf(w.x, xv.x, acc[r]);
                acc[r] = fmaf(w.y, xv.y, acc[r]);
                acc[r] = fmaf(w.z, xv.z, acc[r]);
                acc[r] = fmaf(w.w, xv.w, acc[r]);
            }
        }
    }
#pragma unroll
    for (int r = 0; r < 8; r++) {
        int j = j0 + r;
        float v = acc[r];
        if (bias1) v += bias1[j];
        if (bias2) v += bias2[j];
        if (out_packed) {
            int jj = j + out_row_off;
            out[((jj >> 2) * BB + lane) * 4 + (jj & 3)] = v;
        } else {
            out[(size_t)j * BB + lane] = v;
        }
    }
}

// ---------------- LSTM gate nonlinearity ----------------
__global__ void k_gates(const float* __restrict__ g, float* __restrict__ c,
                        float* __restrict__ hp, float* __restrict__ hpl,
                        float* __restrict__ hbuf)
{
    int i = blockIdx.x * blockDim.x + threadIdx.x;   // over H*B, i = h*32+b
    int h = i >> 5, b = i & 31;
    float ig = g[i];
    float fg = g[HH * BB + i];
    float gg = g[2 * HH * BB + i];
    float og = g[3 * HH * BB + i];
    float cc = c[i];
    float c2 = sigm(fg) * cc + sigm(ig) * tanhf(gg);
    float h2 = sigm(og) * tanhf(c2);
    c[i] = c2;
    hp[((h >> 2) * BB + b) * 4 + (h & 3)] = h2;
    if (hpl)  hpl[i]  = h2;
    if (hbuf) hbuf[i] = h2;
}

// ---------------- init: transpose h0/c0, zero feed region ----------------
__global__ void k_init(const float* __restrict__ h0, const float* __restrict__ c0,
                       float* hp0, float* hp1, float* h1pl, float* c0d, float* c1d, float* x4)
{
    int i = blockIdx.x * blockDim.x + threadIdx.x;   // over H*B
    if (i >= HH * BB) return;
    int h = i >> 5, b = i & 31;
    float v0 = h0[(size_t)b * HH + h];
    float v1 = h0[(size_t)BB * HH + (size_t)b * HH + h];
    int p = ((h >> 2) * BB + b) * 4 + (h & 3);
    hp0[p] = v0;
    hp1[p] = v1;
    h1pl[i] = v1;
    c0d[i] = c0[(size_t)b * HH + h];
    c1d[i] = c0[(size_t)BB * HH + (size_t)b * HH + h];
    x4[EMBD * BB + i] = 0.f;                         // feed=0 at t=0
}

// ---------------- embedding gather into packed x ----------------
__global__ void k_embed(const float* __restrict__ E, const int* __restrict__ toks, int t,
                        float* __restrict__ x4)
{
    int i = blockIdx.x * blockDim.x + threadIdx.x;   // over EMB*B (packed index)
    int b = (i >> 2) & 31;
    int k = (i >> 7) * 4 + (i & 3);
    int tok = toks[t * BB + b];
    x4[i] = E[(size_t)tok * EMBD + k];
}

// ---------------- attention scores: sc[s][b] = key[s][b].htop[b] + pad penalty ----
__global__ void k_scores(const float* __restrict__ keys, const float* __restrict__ htop,
                         const int* __restrict__ toks, float* __restrict__ sc)
{
    int s = blockIdx.x;
    int lane = threadIdx.x & 31, warp = threadIdx.x >> 5;   // 256 threads, 8 warps
    const float* ks = keys + (size_t)s * HH * BB;
    float acc = 0.f;
    for (int h = warp; h < HH; h += 8)
        acc = fmaf(ks[h * BB + lane], htop[h * BB + lane], acc);
    __shared__ float red[8][BB];
    red[warp][lane] = acc;
    __syncthreads();
    if (warp == 0) {
        float v = 0.f;
#pragma unroll
        for (int r = 0; r < 8; r++) v += red[r][lane];
        if (toks[s * BB + lane] == 0) v -= 99999.f;   // PAD mask
        sc[s * BB + lane] = v;
    }
}

// ---------------- softmax over s<=t (per batch) ----------------
__global__ void k_softmax(const float* __restrict__ sc, float* __restrict__ dist, int t)
{
    int b = threadIdx.x;                              // 32 threads
    float m = -1e30f;
    for (int s = 0; s <= t; s++) m = fmaxf(m, sc[s * BB + b]);
    float sum = 0.f;
    for (int s = 0; s <= t; s++) sum += expf(sc[s * BB + b] - m);
    float inv = 1.f / sum;
    for (int s = 0; s <= t; s++) dist[s * BB + b] = expf(sc[s * BB + b] - m) * inv;
}

// ---------------- summary[h][b] = sum_s dist[s][b]*hbuf[s][h][b] (packed out) ----
__global__ void k_summary(const float* __restrict__ dist, const float* __restrict__ hbuf,
                          int t, float* __restrict__ sum4)
{
    int i = blockIdx.x * blockDim.x + threadIdx.x;   // over H*B, planar
    int b = i & 31, h = i >> 5;
    float acc = 0.f;
    for (int s = 0; s <= t; s++)
        acc = fmaf(dist[s * BB + b], hbuf[(size_t)s * HH * BB + i], acc);
    sum4[((h >> 2) * BB + b) * 4 + (h & 3)] = acc;
}

// ---------------- per-batch max & sum(exp) over logits ----------------
__global__ void k_reduce(const float* __restrict__ logits, float* pmax, float* psum)
{
    int b = blockIdx.x;
    int tid = threadIdx.x;                            // 256
    __shared__ float sm[256];
    float m = -1e30f;
    for (int v = tid; v < VV; v += 256) m = fmaxf(m, logits[(size_t)v * BB + b]);
    sm[tid] = m; __syncthreads();
    for (int w = 128; w > 0; w >>= 1) { if (tid < w) sm[tid] = fmaxf(sm[tid], sm[tid + w]); __syncthreads(); }
    float bm = sm[0]; __syncthreads();
    float s = 0.f;
    for (int v = tid; v < VV; v += 256) s += expf(logits[(size_t)v * BB + b] - bm);
    sm[tid] = s; __syncthreads();
    for (int w = 128; w > 0; w >>= 1) { if (tid < w) sm[tid] += sm[tid + w]; __syncthreads(); }
    if (tid == 0) { pmax[b] = bm; psum[b] = sm[0]; }
}

// ---------------- default output: log(cw*EPS + (1-cw)*p[v]) ----------------
__global__ void k_out(const float* __restrict__ logits, const float* __restrict__ pmax,
                      const float* __restrict__ psum, float* __restrict__ out, int t)
{
    int i = blockIdx.x * blockDim.x + threadIdx.x;
    if (i >= BB * VV) return;
    int b = i / VV, v = i - b * VV;
    float m = pmax[b], inv = 1.f / psum[b];
    float pv = expf(logits[(size_t)v * BB + b] - m) * inv;
    float cw = expf(logits[3 * BB + b] - m) * inv;
    out[(size_t)(t * BB + b) * VV + v] = logf(cw * 1e-7f + (1.f - cw) * pv);
}

// ---------------- fixup scattered copy-prob entries (duplicate-aware, no atomics) ----
__global__ void k_fixup(const int* __restrict__ toks, const float* __restrict__ dist,
                        const float* __restrict__ logits, const float* __restrict__ pmax,
                        const float* __restrict__ psum, float* __restrict__ out, int t)
{
    int s = blockIdx.x, b = threadIdx.x;              // (t+1) blocks x 32
    int v = toks[s * BB + b];
    for (int sp = 0; sp < s; sp++)
        if (toks[sp * BB + b] == v) return;           // only first occurrence writes
    float S = 0.f;
    for (int sp = s; sp <= t; sp++)
        if (toks[sp * BB + b] == v) S += dist[sp * BB + b];
    float m = pmax[b], inv = 1.f / psum[b];
    float pv = expf(logits[(size_t)v * BB + b] - m) * inv;
    float cw = expf(logits[3 * BB + b] - m) * inv;
    out[(size_t)(t * BB + b) * VV + v] = logf(cw * (1e-7f + S) + (1.f - cw) * pv);
}

// ---------------- host launch ----------------
extern "C" void kernel_launch(void* const* d_in, const int* in_sizes, int n_in,
                              void* d_out, int out_size)
{
    const int*   toks = (const int*)d_in[0];
    const float* h0   = (const float*)d_in[1];
    const float* c0   = (const float*)d_in[2];
    const float* E    = (const float*)d_in[3];
    const float* Wih0 = (const float*)d_in[4];
    const float* Whh0 = (const float*)d_in[5];
    const float* bih0 = (const float*)d_in[6];
    const float* bhh0 = (const float*)d_in[7];
    const float* Wih1 = (const float*)d_in[8];
    const float* Whh1 = (const float*)d_in[9];
    const float* bih1 = (const float*)d_in[10];
    const float* bhh1 = (const float*)d_in[11];
    const float* Wk   = (const float*)d_in[12];
    const float* bk   = (const float*)d_in[13];
    const float* Wc   = (const float*)d_in[14];
    const float* bc   = (const float*)d_in[15];
    const float* Wp   = (const float*)d_in[16];
    const float* bp   = (const float*)d_in[17];
    float* out = (float*)d_out;

    float *x4, *hp0, *hp1, *h1pl, *c0d, *c1d, *g, *hbuf, *keys, *sc, *dist, *sum4, *logits, *pmax, *psum;
    cudaGetSymbolAddress((void**)&x4,     d_x4);
    cudaGetSymbolAddress((void**)&hp0,    d_hp0);
    cudaGetSymbolAddress((void**)&hp1,    d_hp1);
    cudaGetSymbolAddress((void**)&h1pl,   d_h1pl);
    cudaGetSymbolAddress((void**)&c0d,    d_c0s);
    cudaGetSymbolAddress((void**)&c1d,    d_c1s);
    cudaGetSymbolAddress((void**)&g,      d_g);
    cudaGetSymbolAddress((void**)&hbuf,   d_hbuf);
    cudaGetSymbolAddress((void**)&keys,   d_keys);
    cudaGetSymbolAddress((void**)&sc,     d_sc);
    cudaGetSymbolAddress((void**)&dist,   d_dist);
    cudaGetSymbolAddress((void**)&sum4,   d_sum4);
    cudaGetSymbolAddress((void**)&logits, d_logits);
    cudaGetSymbolAddress((void**)&pmax,   d_pmax);
    cudaGetSymbolAddress((void**)&psum,   d_psum);

    k_init<<<(HH * BB + 255) / 256, 256>>>(h0, c0, hp0, hp1, h1pl, c0d, c1d, x4);

    for (int t = 0; t < TS; t++) {
        k_embed<<<(EMBD * BB) / 256, 256>>>(E, toks, t, x4);
        // LSTM layer 0: g = Wih0.x + Whh0.h0 + biases
        k_gemv<<<G4 / 16, 64>>>(Wih0, KX, KX, x4, Whh0, HH, HH, hp0, bih0, bhh0, g, 0, 0);
        k_gates<<<(HH * BB) / 256, 256>>>(g, c0d, hp0, nullptr, nullptr);
        // LSTM layer 1
        k_gemv<<<G4 / 16, 64>>>(Wih1, HH, HH, hp0, Whh1, HH, HH, hp1, bih1, bhh1, g, 0, 0);
        k_gates<<<(HH * BB) / 256, 256>>>(g, c1d, hp1, h1pl, hbuf + (size_t)t * HH * BB);
        // key[t] = Wk.htop + bk
        k_gemv<<<HH / 16, 64>>>(Wk, HH, HH, hp1, nullptr, 0, 0, nullptr, bk, nullptr,
                                keys + (size_t)t * HH * BB, 0, 0);
        k_scores<<<t + 1, 256>>>(keys, h1pl, toks, sc);
        k_softmax<<<1, 32>>>(sc, dist, t);
        k_summary<<<(HH * BB) / 256, 256>>>(dist, hbuf, t, sum4);
        // comb = Wc.[htop; summary] + bc  -> written packed into feed region of x4
        k_gemv<<<HH / 16, 64>>>(Wc, HH, 2 * HH, hp1, Wc + HH, HH, 2 * HH, sum4, bc, nullptr,
                                x4, 1, EMBD);
        // logits = Wp.comb + bp
        k_gemv<<<VV / 16, 64>>>(Wp, HH, HH, x4 + EMBD * BB, nullptr, 0, 0, nullptr, bp, nullptr,
                                logits, 0, 0);
        k_reduce<<<BB, 256>>>(logits, pmax, psum);
        k_out<<<(BB * VV + 255) / 256, 256>>>(logits, pmax, psum, out, t);
        k_fixup<<<t + 1, BB>>>(toks, dist, logits, pmax, psum, out, t);
    }
}

// round 4
// speedup vs baseline: 3.2122x; 3.2082x over previous
#include <cuda_runtime.h>
#include <math.h>

#define TS   64
#define BB   32
#define VV   32000
#define HH   1024
#define EMBD 512
#define G4   4096
#define HB   32768          // HH*BB

// ---------------- device scratch ----------------
__device__ float d_emb[(size_t)TS * EMBD * BB];   // [t][k][b]
__device__ float d_comb[HB];                      // planar [k][b]
__device__ float d_h0p[HB];
__device__ float d_h1i[HB];
__device__ float d_c0p[HB], d_c1p[HB];
__device__ float d_g[(size_t)G4 * BB];
__device__ float d_hbuf[(size_t)TS * HB];
__device__ float d_keys[(size_t)TS * HB];
__device__ float d_sc[TS * BB], d_dist[TS * BB];
__device__ float d_sumv[HB];
__device__ float d_logits[(size_t)VV * BB];       // [v][b]
__device__ float d_red[125 * 64];
__device__ float d_pmax[BB], d_pinv[BB], d_cwv[BB];

__device__ __forceinline__ float sigm(float x) { return 1.f / (1.f + expf(-x)); }

// ---- packed fp32x2 FMA (sm_103a) ----
__device__ __forceinline__ void ffma2(unsigned long long& d, unsigned long long a,
                                      unsigned long long x) {
    asm("fma.rn.f32x2 %0, %1, %2, %0;" : "+l"(d) : "l"(a), "l"(x));
}
__device__ __forceinline__ unsigned long long pack2(float x) {
    unsigned long long r; unsigned int xi = __float_as_uint(x);
    asm("mov.b64 %0, {%1, %1};" : "=l"(r) : "r"(xi));
    return r;
}
__device__ __forceinline__ void unpack2(unsigned long long v, float& lo, float& hi) {
    unsigned int a, b;
    asm("mov.b64 {%0, %1}, %2;" : "=r"(a), "=r"(b) : "l"(v));
    lo = __uint_as_float(a); hi = __uint_as_float(b);
}

// ---------------- tiled GEMM: out[j][b] += sum over up to 3 (A,X) segments ----
// A row-major [rows x lda]; X planar [K x 32]. 256 threads, JT rows/block.
// k-tile 32, double-buffered smem, register prefetch, FFMA2 row-pairs.
template<int JT>
__global__ void __launch_bounds__(256) k_gemm(
    const float* __restrict__ A0, const float* __restrict__ X0, int lda0, int K0,
    const float* __restrict__ A1, const float* __restrict__ X1, int lda1, int K1,
    const float* __restrict__ A2, const float* __restrict__ X2, int lda2, int K2,
    const float* __restrict__ bias1, const float* __restrict__ bias2,
    float* __restrict__ out)
{
    constexpr int R   = JT / 8;       // rows per thread
    constexpr int PR  = R / 2;        // FFMA2 pairs per thread
    constexpr int AST = JT + 4;       // smem row stride (floats)
    constexpr int NCH = JT / 32;      // A float4 chunks per thread per tile

    __shared__ __align__(16) float As[2][32 * AST];
    __shared__ float Xs[2][32 * 33];

    const int tid  = threadIdx.x;
    const int b    = tid & 31;
    const int rg   = tid >> 5;
    const int j0   = blockIdx.x * JT;
    const int arow = tid >> 3;        // 0..31
    const int aq   = (tid & 7) << 2;  // k-offset of float4 in tile
    const int xk   = tid >> 5;        // 0..7

    unsigned long long acc[PR];
#pragma unroll
    for (int p = 0; p < PR; p++) acc[p] = 0ull;

    float4 av[NCH];
    float  xv[4];
    int buf = 0;

    for (int seg = 0; seg < 3; seg++) {
        const float* A; const float* X; int lda, K;
        if (seg == 0)      { A = A0; X = X0; lda = lda0; K = K0; }
        else if (seg == 1) { A = A1; X = X1; lda = lda1; K = K1; }
        else               { A = A2; X = X2; lda = lda2; K = K2; }
        if (!A) continue;
        const int NT = K >> 5;

        // prefetch tile 0
#pragma unroll
        for (int c = 0; c < NCH; c++)
            av[c] = *(const float4*)(A + (size_t)(j0 + arow + 32 * c) * lda + aq);
#pragma unroll
        for (int i = 0; i < 4; i++)
            xv[i] = X[(size_t)(xk + 8 * i) * BB + b];

        for (int kt = 0; kt < NT; kt++) {
            // store prefetched tile to smem[buf]
#pragma unroll
            for (int c = 0; c < NCH; c++) {
                const int r = arow + 32 * c;
                As[buf][(aq + 0) * AST + r] = av[c].x;
                As[buf][(aq + 1) * AST + r] = av[c].y;
                As[buf][(aq + 2) * AST + r] = av[c].z;
                As[buf][(aq + 3) * AST + r] = av[c].w;
            }
#pragma unroll
            for (int i = 0; i < 4; i++)
                Xs[buf][(xk + 8 * i) * 33 + b] = xv[i];
            __syncthreads();

            if (kt + 1 < NT) {
                const int k0 = (kt + 1) << 5;
#pragma unroll
                for (int c = 0; c < NCH; c++)
                    av[c] = *(const float4*)(A + (size_t)(j0 + arow + 32 * c) * lda + k0 + aq);
#pragma unroll
                for (int i = 0; i < 4; i++)
                    xv[i] = X[(size_t)(k0 + xk + 8 * i) * BB + b];
            }

#pragma unroll
            for (int kk = 0; kk < 32; kk++) {
                unsigned long long xp = pack2(Xs[buf][kk * 33 + b]);
                const float* ab = &As[buf][kk * AST + rg * R];
#pragma unroll
                for (int q = 0; q < PR / 2; q++) {
                    ulonglong2 u = *(const ulonglong2*)(ab + (q << 2));
                    ffma2(acc[2 * q],     u.x, xp);
                    ffma2(acc[2 * q + 1], u.y, xp);
                }
            }
            buf ^= 1;
            __syncthreads();
        }
    }

#pragma unroll
    for (int p = 0; p < PR; p++) {
        float lo, hi;
        unpack2(acc[p], lo, hi);
        const int j = j0 + rg * R + 2 * p;
        if (bias1) { lo += bias1[j]; hi += bias1[j + 1]; }
        if (bias2) { lo += bias2[j]; hi += bias2[j + 1]; }
        out[(size_t)j * BB + b]       = lo;
        out[(size_t)(j + 1) * BB + b] = hi;
    }
}

// ---------------- embed all timesteps once ----------------
__global__ void k_embed_all(const float* __restrict__ E, const int* __restrict__ toks,
                            float* __restrict__ emb)
{
    int i = blockIdx.x * 256 + threadIdx.x;    // TS*EMBD*BB
    int b = i & 31, k = (i >> 5) & (EMBD - 1), t = i >> 14;
    emb[i] = E[(size_t)toks[t * BB + b] * EMBD + k];
}

// ---------------- init ----------------
__global__ void k_init(const float* __restrict__ h0, const float* __restrict__ c0,
                       float* h0p, float* h1i, float* c0p, float* c1p, float* comb)
{
    int i = blockIdx.x * 256 + threadIdx.x;    // HB
    int h = i >> 5, b = i & 31;
    h0p[i]  = h0[(size_t)b * HH + h];
    h1i[i]  = h0[(size_t)(BB + b) * HH + h];
    c0p[i]  = c0[(size_t)b * HH + h];
    c1p[i]  = c0[(size_t)(BB + b) * HH + h];
    comb[i] = 0.f;
}

// ---------------- LSTM gates ----------------
__global__ void k_gates(const float* __restrict__ g, float* __restrict__ c,
                        float* __restrict__ hout)
{
    int i = blockIdx.x * 256 + threadIdx.x;    // HB
    float ig = g[i], fg = g[HB + i], gg = g[2 * HB + i], og = g[3 * HB + i];
    float c2 = sigm(fg) * c[i] + sigm(ig) * tanhf(gg);
    c[i] = c2;
    hout[i] = sigm(og) * tanhf(c2);
}

// ---------------- scores ----------------
__global__ void __launch_bounds__(256) k_scores(const float* __restrict__ keys,
        const float* __restrict__ htop, const int* __restrict__ toks,
        float* __restrict__ sc)
{
    int s = blockIdx.x;
    int lane = threadIdx.x & 31, w = threadIdx.x >> 5;
    const float* ks = keys + (size_t)s * HB;
    float acc = 0.f;
    for (int h = w; h < HH; h += 8)
        acc = fmaf(ks[h * BB + lane], htop[h * BB + lane], acc);
    __shared__ float red[8][BB];
    red[w][lane] = acc;
    __syncthreads();
    if (w == 0) {
        float v = acc;
#pragma unroll
        for (int r = 1; r < 8; r++) v += red[r][lane];
        if (toks[s * BB + lane] == 0) v -= 99999.f;
        sc[s * BB + lane] = v;
    }
}

// ---------------- softmax over s<=t ----------------
__global__ void k_softmax(const float* __restrict__ sc, float* __restrict__ dist, int t)
{
    int b = threadIdx.x;
    float m = -1e30f;
    for (int s = 0; s <= t; s++) m = fmaxf(m, sc[s * BB + b]);
    float sum = 0.f;
    for (int s = 0; s <= t; s++) sum += expf(sc[s * BB + b] - m);
    float inv = 1.f / sum;
    for (int s = 0; s <= t; s++) dist[s * BB + b] = expf(sc[s * BB + b] - m) * inv;
}

// ---------------- summary ----------------
__global__ void k_summary(const float* __restrict__ dist, const float* __restrict__ hbuf,
                          int t, float* __restrict__ sum)
{
    int i = blockIdx.x * 256 + threadIdx.x;    // HB
    int b = i & 31;
    float acc = 0.f;
    for (int s = 0; s <= t; s++)
        acc = fmaf(dist[s * BB + b], hbuf[(size_t)s * HB + i], acc);
    sum[i] = acc;
}

// ---------------- coalesced online (max,sum) over logits ----------------
__global__ void k_reduce1(const float* __restrict__ logits, float* __restrict__ part)
{
    int v0 = blockIdx.x * 256;                 // 125 blocks
    int lane = threadIdx.x & 31, w = threadIdx.x >> 5;
    float m = -1e30f, s = 0.f;
    for (int k = 0; k < 32; k++) {
        float x = logits[(size_t)(v0 + (k << 3) + w) * BB + lane];
        float m2 = fmaxf(m, x);
        s = s * expf(m - m2) + expf(x - m2);
        m = m2;
    }
    __shared__ float sm[8][BB], ss[8][BB];
    sm[w][lane] = m; ss[w][lane] = s;
    __syncthreads();
    if (w == 0) {
#pragma unroll
        for (int r = 1; r < 8; r++) {
            float m2 = fmaxf(m, sm[r][lane]);
            s = s * expf(m - m2) + ss[r][lane] * expf(sm[r][lane] - m2);
            m = m2;
        }
        part[blockIdx.x * 64 + lane]      = m;
        part[blockIdx.x * 64 + 32 + lane] = s;
    }
}

__global__ void k_reduce2(const float* __restrict__ part, const float* __restrict__ logits,
                          float* pmax, float* pinv, float* cw)
{
    int b = threadIdx.x;
    float m = -1e30f, s = 0.f;
    for (int i = 0; i < 125; i++) {
        float pm = part[i * 64 + b], ps = part[i * 64 + 32 + b];
        float m2 = fmaxf(m, pm);
        s = s * expf(m - m2) + ps * expf(pm - m2);
        m = m2;
    }
    float inv = 1.f / s;
    pmax[b] = m; pinv[b] = inv;
    cw[b] = expf(logits[3 * BB + b] - m) * inv;
}

// ---------------- output: smem transpose, coalesced both ways ----------------
__global__ void __launch_bounds__(256) k_out(const float* __restrict__ logits,
        const float* __restrict__ pmax, const float* __restrict__ pinv,
        const float* __restrict__ cw, float* __restrict__ out, int t)
{
    __shared__ float tile[128][33];
    int v0 = blockIdx.x * 128;                 // 250 blocks
    int lane = threadIdx.x & 31, w = threadIdx.x >> 5;
    float m = pmax[lane], inv = pinv[lane], c = cw[lane];
    float ce = c * 1e-7f, l1c = 1.f - c;
#pragma unroll
    for (int k = 0; k < 16; k++) {
        int vr = (k << 3) + w;
        float pv = expf(logits[(size_t)(v0 + vr) * BB + lane] - m) * inv;
        tile[vr][lane] = logf(ce + l1c * pv);
    }
    __syncthreads();
    int bo = threadIdx.x >> 3, q = threadIdx.x & 7;
    float* op = out + (size_t)(t * BB + bo) * VV + v0;
#pragma unroll
    for (int i = 0; i < 4; i++) {
        int vb = (q + (i << 3)) << 2;
        *(float4*)(op + vb) = make_float4(tile[vb][bo], tile[vb + 1][bo],
                                          tile[vb + 2][bo], tile[vb + 3][bo]);
    }
}

// ---------------- copy-scatter fixup ----------------
__global__ void k_fixup(const int* __restrict__ toks, const float* __restrict__ dist,
                        const float* __restrict__ logits, const float* __restrict__ pmax,
                        const float* __restrict__ pinv, const float* __restrict__ cw,
                        float* __restrict__ out, int t)
{
    int s = blockIdx.x, b = threadIdx.x;
    int v = toks[s * BB + b];
    for (int sp = 0; sp < s; sp++)
        if (toks[sp * BB + b] == v) return;
    float S = 0.f;
    for (int sp = s; sp <= t; sp++)
        if (toks[sp * BB + b] == v) S += dist[sp * BB + b];
    float pv = expf(logits[(size_t)v * BB + b] - pmax[b]) * pinv[b];
    float c = cw[b];
    out[(size_t)(t * BB + b) * VV + v] = logf(c * (1e-7f + S) + (1.f - c) * pv);
}

// ---------------- host ----------------
extern "C" void kernel_launch(void* const* d_in, const int* in_sizes, int n_in,
                              void* d_out, int out_size)
{
    const int*   toks = (const int*)d_in[0];
    const float* h0   = (const float*)d_in[1];
    const float* c0   = (const float*)d_in[2];
    const float* E    = (const float*)d_in[3];
    const float* Wih0 = (const float*)d_in[4];
    const float* Whh0 = (const float*)d_in[5];
    const float* bih0 = (const float*)d_in[6];
    const float* bhh0 = (const float*)d_in[7];
    const float* Wih1 = (const float*)d_in[8];
    const float* Whh1 = (const float*)d_in[9];
    const float* bih1 = (const float*)d_in[10];
    const float* bhh1 = (const float*)d_in[11];
    const float* Wk   = (const float*)d_in[12];
    const float* bk   = (const float*)d_in[13];
    const float* Wc   = (const float*)d_in[14];
    const float* bc   = (const float*)d_in[15];
    const float* Wp   = (const float*)d_in[16];
    const float* bp   = (const float*)d_in[17];
    float* out = (float*)d_out;

    float *emb, *comb, *h0p, *h1i, *c0p, *c1p, *g, *hbuf, *keys, *sc, *dist;
    float *sumv, *logits, *red, *pmax, *pinv, *cwv;
    cudaGetSymbolAddress((void**)&emb,    d_emb);
    cudaGetSymbolAddress((void**)&comb,   d_comb);
    cudaGetSymbolAddress((void**)&h0p,    d_h0p);
    cudaGetSymbolAddress((void**)&h1i,    d_h1i);
    cudaGetSymbolAddress((void**)&c0p,    d_c0p);
    cudaGetSymbolAddress((void**)&c1p,    d_c1p);
    cudaGetSymbolAddress((void**)&g,      d_g);
    cudaGetSymbolAddress((void**)&hbuf,   d_hbuf);
    cudaGetSymbolAddress((void**)&keys,   d_keys);
    cudaGetSymbolAddress((void**)&sc,     d_sc);
    cudaGetSymbolAddress((void**)&dist,   d_dist);
    cudaGetSymbolAddress((void**)&sumv,   d_sumv);
    cudaGetSymbolAddress((void**)&logits, d_logits);
    cudaGetSymbolAddress((void**)&red,    d_red);
    cudaGetSymbolAddress((void**)&pmax,   d_pmax);
    cudaGetSymbolAddress((void**)&pinv,   d_pinv);
    cudaGetSymbolAddress((void**)&cwv,    d_cwv);

    k_embed_all<<<(TS * EMBD * BB) / 256, 256>>>(E, toks, emb);
    k_init<<<HB / 256, 256>>>(h0, c0, h0p, h1i, c0p, c1p, comb);

    for (int t = 0; t < TS; t++) {
        float* htop = hbuf + (size_t)t * HB;
        const float* h1prev = t ? hbuf + (size_t)(t - 1) * HB : h1i;
        const float* emb_t  = emb + (size_t)t * EMBD * BB;

        // LSTM0: g = Wih0[:, :512]@emb + Wih0[:, 512:]@comb + Whh0@h0 + biases
        k_gemm<32><<<G4 / 32, 256>>>(Wih0, emb_t, 1536, 512,
                                     Wih0 + 512, comb, 1536, 1024,
                                     Whh0, h0p, 1024, 1024, bih0, bhh0, g);
        k_gates<<<HB / 256, 256>>>(g, c0p, h0p);
        // LSTM1
        k_gemm<32><<<G4 / 32, 256>>>(Wih1, h0p, 1024, 1024,
                                     Whh1, h1prev, 1024, 1024,
                                     nullptr, nullptr, 0, 0, bih1, bhh1, g);
        k_gates<<<HB / 256, 256>>>(g, c1p, htop);
        // keys[t] = Wk@htop + bk
        k_gemm<32><<<HH / 32, 256>>>(Wk, htop, 1024, 1024,
                                     nullptr, nullptr, 0, 0,
                                     nullptr, nullptr, 0, 0, bk, nullptr,
                                     keys + (size_t)t * HB);
        k_scores<<<t + 1, 256>>>(keys, htop, toks, sc);
        k_softmax<<<1, 32>>>(sc, dist, t);
        k_summary<<<HB / 256, 256>>>(dist, hbuf, t, sumv);
        // comb = Wc@[htop; summary] + bc
        k_gemm<32><<<HH / 32, 256>>>(Wc, htop, 2048, 1024,
                                     Wc + 1024, sumv, 2048, 1024,
                                     nullptr, nullptr, 0, 0, bc, nullptr, comb);
        // logits = Wp@comb + bp
        k_gemm<64><<<VV / 64, 256>>>(Wp, comb, 1024, 1024,
                                     nullptr, nullptr, 0, 0,
                                     nullptr, nullptr, 0, 0, bp, nullptr, logits);
        k_reduce1<<<125, 256>>>(logits, red);
        k_reduce2<<<1, 32>>>(red, logits, pmax, pinv, cwv);
        k_out<<<250, 256>>>(logits, pmax, pinv, cwv, out, t);
        k_fixup<<<t + 1, BB>>>(toks, dist, logits, pmax, pinv, cwv, out, t);
    }
}

// round 5
// speedup vs baseline: 3.6904x; 1.1489x over previous
#include <cuda_runtime.h>
#include <math.h>

#define TS   64
#define BB   32
#define VV   32000
#define HH   1024
#define EMBD 512
#define G4   4096
#define HB   32768          // HH*BB

// ---------------- device scratch ----------------
__device__ float d_emb[(size_t)TS * EMBD * BB];   // [t][k][b]
__device__ float d_comb[HB];
__device__ float d_h0p[HB];
__device__ float d_h1i[HB];
__device__ float d_c0p[HB], d_c1p[HB];
__device__ float d_g[4 * (size_t)G4 * BB];        // 4 partial planes
__device__ float d_kp[4 * (size_t)HB];            // key partials
__device__ float d_cp[4 * (size_t)HB];            // comb partials
__device__ float d_hbuf[(size_t)TS * HB];
__device__ float d_keys[(size_t)TS * HB];
__device__ float d_sc[TS * BB], d_dist[TS * BB];
__device__ float d_sumv[HB];
__device__ float d_logits[(size_t)VV * BB];       // [v][b]
__device__ float d_red[125 * 64];
__device__ float d_pmax[BB], d_pinv[BB], d_cwv[BB];

__device__ __forceinline__ float sigm(float x) { return 1.f / (1.f + expf(-x)); }

// ---- packed fp32x2 FMA (sm_103a) ----
__device__ __forceinline__ void ffma2(unsigned long long& d, unsigned long long a,
                                      unsigned long long x) {
    asm("fma.rn.f32x2 %0, %1, %2, %0;" : "+l"(d) : "l"(a), "l"(x));
}
__device__ __forceinline__ unsigned long long pack2(float x) {
    unsigned long long r; unsigned int xi = __float_as_uint(x);
    asm("mov.b64 %0, {%1, %1};" : "=l"(r) : "r"(xi));
    return r;
}
__device__ __forceinline__ void unpack2(unsigned long long v, float& lo, float& hi) {
    unsigned int a, b;
    asm("mov.b64 {%0, %1}, %2;" : "=r"(a), "=r"(b) : "l"(v));
    lo = __uint_as_float(a); hi = __uint_as_float(b);
}

// ---------------- tiled GEMM with k-split over gridDim.y ----------------
// out[y-plane][j][b] = sum over k-tiles [y*tps, y*tps+tps) of virtual
// concatenated segments. Split 0 adds biases. 256 threads, JT rows/block.
template<int JT>
__global__ void __launch_bounds__(256) k_gemm(
    const float* __restrict__ A0, const float* __restrict__ X0, int lda0, int t0,
    const float* __restrict__ A1, const float* __restrict__ X1, int lda1, int t1,
    const float* __restrict__ A2, const float* __restrict__ X2, int lda2, int t2,
    int tps, const float* __restrict__ bias1, const float* __restrict__ bias2,
    float* __restrict__ out, long long outPlane)
{
    constexpr int R   = JT / 8;
    constexpr int PR  = R / 2;
    constexpr int AST = JT + 4;
    constexpr int NCH = JT / 32;

    __shared__ __align__(16) float As[2][32 * AST];
    __shared__ float Xs[2][32 * 33];

    const int tid  = threadIdx.x;
    const int b    = tid & 31;
    const int rg   = tid >> 5;
    const int j0   = blockIdx.x * JT;
    const int arow = tid >> 3;
    const int aq   = (tid & 7) << 2;
    const int xk   = tid >> 5;

    const int total = t0 + t1 + t2;
    const int g0 = blockIdx.y * tps;
    const int g1 = min(total, g0 + tps);

    unsigned long long acc[PR];
#pragma unroll
    for (int p = 0; p < PR; p++) acc[p] = 0ull;

    float4 av[NCH];
    float  xv[4];

    auto fetch = [&](int g) {
        const float* A; const float* X; int lda, lk;
        if (g < t0)            { A = A0; X = X0; lda = lda0; lk = g; }
        else if (g < t0 + t1)  { A = A1; X = X1; lda = lda1; lk = g - t0; }
        else                   { A = A2; X = X2; lda = lda2; lk = g - t0 - t1; }
        const int k0 = lk << 5;
#pragma unroll
        for (int c = 0; c < NCH; c++)
            av[c] = *(const float4*)(A + (size_t)(j0 + arow + 32 * c) * lda + k0 + aq);
#pragma unroll
        for (int i = 0; i < 4; i++)
            xv[i] = X[(size_t)(k0 + xk + 8 * i) * BB + b];
    };

    int buf = 0;
    if (g0 < g1) fetch(g0);
    for (int g = g0; g < g1; g++) {
#pragma unroll
        for (int c = 0; c < NCH; c++) {
            const int r = arow + 32 * c;
            As[buf][(aq + 0) * AST + r] = av[c].x;
            As[buf][(aq + 1) * AST + r] = av[c].y;
            As[buf][(aq + 2) * AST + r] = av[c].z;
            As[buf][(aq + 3) * AST + r] = av[c].w;
        }
#pragma unroll
        for (int i = 0; i < 4; i++)
            Xs[buf][(xk + 8 * i) * 33 + b] = xv[i];
        __syncthreads();

        if (g + 1 < g1) fetch(g + 1);

#pragma unroll
        for (int kk = 0; kk < 32; kk++) {
            unsigned long long xp = pack2(Xs[buf][kk * 33 + b]);
            const float* ab = &As[buf][kk * AST + rg * R];
#pragma unroll
            for (int q = 0; q < PR / 2; q++) {
                ulonglong2 u = *(const ulonglong2*)(ab + (q << 2));
                ffma2(acc[2 * q],     u.x, xp);
                ffma2(acc[2 * q + 1], u.y, xp);
            }
        }
        buf ^= 1;
        __syncthreads();
    }

    float* outp = out + blockIdx.y * outPlane;
#pragma unroll
    for (int p = 0; p < PR; p++) {
        float lo, hi;
        unpack2(acc[p], lo, hi);
        const int j = j0 + rg * R + 2 * p;
        if (blockIdx.y == 0) {
            if (bias1) { lo += bias1[j]; hi += bias1[j + 1]; }
            if (bias2) { lo += bias2[j]; hi += bias2[j + 1]; }
        }
        outp[(size_t)j * BB + b]       = lo;
        outp[(size_t)(j + 1) * BB + b] = hi;
    }
}

// ---------------- embed all timesteps once ----------------
__global__ void k_embed_all(const float* __restrict__ E, const int* __restrict__ toks,
                            float* __restrict__ emb)
{
    int i = blockIdx.x * 256 + threadIdx.x;
    int b = i & 31, k = (i >> 5) & (EMBD - 1), t = i >> 14;
    emb[i] = E[(size_t)toks[t * BB + b] * EMBD + k];
}

// ---------------- init ----------------
__global__ void k_init(const float* __restrict__ h0, const float* __restrict__ c0,
                       float* h0p, float* h1i, float* c0p, float* c1p, float* comb)
{
    int i = blockIdx.x * 256 + threadIdx.x;
    int h = i >> 5, b = i & 31;
    h0p[i]  = h0[(size_t)b * HH + h];
    h1i[i]  = h0[(size_t)(BB + b) * HH + h];
    c0p[i]  = c0[(size_t)b * HH + h];
    c1p[i]  = c0[(size_t)(BB + b) * HH + h];
    comb[i] = 0.f;
}

// ---------------- LSTM gates: sum 4 partial planes + nonlinearity ----------------
__global__ void k_gates(const float* __restrict__ gp, float* __restrict__ c,
                        float* __restrict__ hout)
{
    int i = blockIdx.x * 256 + threadIdx.x;    // HB
    float g[4];
#pragma unroll
    for (int m = 0; m < 4; m++) {
        size_t o = (size_t)m * HB + i;
        g[m] = gp[o] + gp[(size_t)G4 * BB + o] + gp[2 * (size_t)G4 * BB + o]
             + gp[3 * (size_t)G4 * BB + o];
    }
    float c2 = sigm(g[1]) * c[i] + sigm(g[0]) * tanhf(g[2]);
    c[i] = c2;
    hout[i] = sigm(g[3]) * tanhf(c2);
}

// ---------------- scores (+ finalize keys[t] from partials at s==t) ----------------
__global__ void __launch_bounds__(256) k_scores(float* __restrict__ keys,
        const float* __restrict__ kp, const float* __restrict__ htop,
        const int* __restrict__ toks, float* __restrict__ sc, int t)
{
    int s = blockIdx.x;
    int lane = threadIdx.x & 31, w = threadIdx.x >> 5;
    float acc = 0.f;
    if (s == t) {
        float* kf = keys + (size_t)t * HB;
        for (int h = w; h < HH; h += 8) {
            int i = h * BB + lane;
            float v = kp[i] + kp[HB + i] + kp[2 * HB + i] + kp[3 * HB + i];
            kf[i] = v;
            acc = fmaf(v, htop[i], acc);
        }
    } else {
        const float* ks = keys + (size_t)s * HB;
        for (int h = w; h < HH; h += 8)
            acc = fmaf(ks[h * BB + lane], htop[h * BB + lane], acc);
    }
    __shared__ float red[8][BB];
    red[w][lane] = acc;
    __syncthreads();
    if (w == 0) {
        float v = acc;
#pragma unroll
        for (int r = 1; r < 8; r++) v += red[r][lane];
        if (toks[s * BB + lane] == 0) v -= 99999.f;
        sc[s * BB + lane] = v;
    }
}

// ---------------- summary (softmax inlined) + dist ----------------
__global__ void k_summary(const float* __restrict__ sc, const float* __restrict__ hbuf,
                          int t, float* __restrict__ dist, float* __restrict__ sum)
{
    int i = blockIdx.x * 256 + threadIdx.x;    // HB
    int b = i & 31;
    float m = -1e30f;
    for (int s = 0; s <= t; s++) m = fmaxf(m, sc[s * BB + b]);
    float ssum = 0.f;
    for (int s = 0; s <= t; s++) ssum += expf(sc[s * BB + b] - m);
    float inv = 1.f / ssum;
    float acc = 0.f;
    for (int s = 0; s <= t; s++)
        acc = fmaf(expf(sc[s * BB + b] - m) * inv, hbuf[(size_t)s * HB + i], acc);
    sum[i] = acc;
    if (i < BB)
        for (int s = 0; s <= t; s++) dist[s * BB + i] = expf(sc[s * BB + i] - m) * inv;
}

// ---------------- comb = sum of 4 partials ----------------
__global__ void k_fincomb(const float* __restrict__ cp, float* __restrict__ comb)
{
    int i = blockIdx.x * 256 + threadIdx.x;    // HB
    comb[i] = cp[i] + cp[HB + i] + cp[2 * HB + i] + cp[3 * HB + i];
}

// ---------------- coalesced online (max,sum) over logits ----------------
__global__ void k_reduce1(const float* __restrict__ logits, float* __restrict__ part)
{
    int v0 = blockIdx.x * 256;
    int lane = threadIdx.x & 31, w = threadIdx.x >> 5;
    float m = -1e30f, s = 0.f;
    for (int k = 0; k < 32; k++) {
        float x = logits[(size_t)(v0 + (k << 3) + w) * BB + lane];
        float m2 = fmaxf(m, x);
        s = s * expf(m - m2) + expf(x - m2);
        m = m2;
    }
    __shared__ float sm[8][BB], ss[8][BB];
    sm[w][lane] = m; ss[w][lane] = s;
    __syncthreads();
    if (w == 0) {
#pragma unroll
        for (int r = 1; r < 8; r++) {
            float m2 = fmaxf(m, sm[r][lane]);
            s = s * expf(m - m2) + ss[r][lane] * expf(sm[r][lane] - m2);
            m = m2;
        }
        part[blockIdx.x * 64 + lane]      = m;
        part[blockIdx.x * 64 + 32 + lane] = s;
    }
}

__global__ void k_reduce2(const float* __restrict__ part, const float* __restrict__ logits,
                          float* pmax, float* pinv, float* cw)
{
    int b = threadIdx.x;
    float m = -1e30f, s = 0.f;
    for (int i = 0; i < 125; i++) {
        float pm = part[i * 64 + b], ps = part[i * 64 + 32 + b];
        float m2 = fmaxf(m, pm);
        s = s * expf(m - m2) + ps * expf(pm - m2);
        m = m2;
    }
    float inv = 1.f / s;
    pmax[b] = m; pinv[b] = inv;
    cw[b] = expf(logits[3 * BB + b] - m) * inv;
}

// ---------------- output: smem transpose, coalesced both ways ----------------
__global__ void __launch_bounds__(256) k_out(const float* __restrict__ logits,
        const float* __restrict__ pmax, const float* __restrict__ pinv,
        const float* __restrict__ cw, float* __restrict__ out, int t)
{
    __shared__ float tile[128][33];
    int v0 = blockIdx.x * 128;
    int lane = threadIdx.x & 31, w = threadIdx.x >> 5;
    float m = pmax[lane], inv = pinv[lane], c = cw[lane];
    float ce = c * 1e-7f, l1c = 1.f - c;
#pragma unroll
    for (int k = 0; k < 16; k++) {
        int vr = (k << 3) + w;
        float pv = expf(logits[(size_t)(v0 + vr) * BB + lane] - m) * inv;
        tile[vr][lane] = logf(ce + l1c * pv);
    }
    __syncthreads();
    int bo = threadIdx.x >> 3, q = threadIdx.x & 7;
    float* op = out + (size_t)(t * BB + bo) * VV + v0;
#pragma unroll
    for (int i = 0; i < 4; i++) {
        int vb = (q + (i << 3)) << 2;
        *(float4*)(op + vb) = make_float4(tile[vb][bo], tile[vb + 1][bo],
                                          tile[vb + 2][bo], tile[vb + 3][bo]);
    }
}

// ---------------- copy-scatter fixup ----------------
__global__ void k_fixup(const int* __restrict__ toks, const float* __restrict__ dist,
                        const float* __restrict__ logits, const float* __restrict__ pmax,
                        const float* __restrict__ pinv, const float* __restrict__ cw,
                        float* __restrict__ out, int t)
{
    int s = blockIdx.x, b = threadIdx.x;
    int v = toks[s * BB + b];
    for (int sp = 0; sp < s; sp++)
        if (toks[sp * BB + b] == v) return;
    float S = 0.f;
    for (int sp = s; sp <= t; sp++)
        if (toks[sp * BB + b] == v) S += dist[sp * BB + b];
    float pv = expf(logits[(size_t)v * BB + b] - pmax[b]) * pinv[b];
    float c = cw[b];
    out[(size_t)(t * BB + b) * VV + v] = logf(c * (1e-7f + S) + (1.f - c) * pv);
}

// ---------------- host ----------------
extern "C" void kernel_launch(void* const* d_in, const int* in_sizes, int n_in,
                              void* d_out, int out_size)
{
    const int*   toks = (const int*)d_in[0];
    const float* h0   = (const float*)d_in[1];
    const float* c0   = (const float*)d_in[2];
    const float* E    = (const float*)d_in[3];
    const float* Wih0 = (const float*)d_in[4];
    const float* Whh0 = (const float*)d_in[5];
    const float* bih0 = (const float*)d_in[6];
    const float* bhh0 = (const float*)d_in[7];
    const float* Wih1 = (const float*)d_in[8];
    const float* Whh1 = (const float*)d_in[9];
    const float* bih1 = (const float*)d_in[10];
    const float* bhh1 = (const float*)d_in[11];
    const float* Wk   = (const float*)d_in[12];
    const float* bk   = (const float*)d_in[13];
    const float* Wc   = (const float*)d_in[14];
    const float* bc   = (const float*)d_in[15];
    const float* Wp   = (const float*)d_in[16];
    const float* bp   = (const float*)d_in[17];
    float* out = (float*)d_out;

    float *emb, *comb, *h0p, *h1i, *c0p, *c1p, *g, *kp, *cp, *hbuf, *keys;
    float *sc, *dist, *sumv, *logits, *red, *pmax, *pinv, *cwv;
    cudaGetSymbolAddress((void**)&emb,    d_emb);
    cudaGetSymbolAddress((void**)&comb,   d_comb);
    cudaGetSymbolAddress((void**)&h0p,    d_h0p);
    cudaGetSymbolAddress((void**)&h1i,    d_h1i);
    cudaGetSymbolAddress((void**)&c0p,    d_c0p);
    cudaGetSymbolAddress((void**)&c1p,    d_c1p);
    cudaGetSymbolAddress((void**)&g,      d_g);
    cudaGetSymbolAddress((void**)&kp,     d_kp);
    cudaGetSymbolAddress((void**)&cp,     d_cp);
    cudaGetSymbolAddress((void**)&hbuf,   d_hbuf);
    cudaGetSymbolAddress((void**)&keys,   d_keys);
    cudaGetSymbolAddress((void**)&sc,     d_sc);
    cudaGetSymbolAddress((void**)&dist,   d_dist);
    cudaGetSymbolAddress((void**)&sumv,   d_sumv);
    cudaGetSymbolAddress((void**)&logits, d_logits);
    cudaGetSymbolAddress((void**)&red,    d_red);
    cudaGetSymbolAddress((void**)&pmax,   d_pmax);
    cudaGetSymbolAddress((void**)&pinv,   d_pinv);
    cudaGetSymbolAddress((void**)&cwv,    d_cwv);

    const long long GP = (long long)G4 * BB;

    k_embed_all<<<(TS * EMBD * BB) / 256, 256>>>(E, toks, emb);
    k_init<<<HB / 256, 256>>>(h0, c0, h0p, h1i, c0p, c1p, comb);

    for (int t = 0; t < TS; t++) {
        float* htop = hbuf + (size_t)t * HB;
        const float* h1prev = t ? hbuf + (size_t)(t - 1) * HB : h1i;
        const float* emb_t  = emb + (size_t)t * EMBD * BB;

        // LSTM0: 80 k-tiles (emb 16 | comb 32 | h0 32), 4 splits x 20
        k_gemm<32><<<dim3(G4 / 32, 4), 256>>>(
            Wih0, emb_t, 1536, 16,
            Wih0 + 512, comb, 1536, 32,
            Whh0, h0p, 1024, 32,
            20, bih0, bhh0, g, GP);
        k_gates<<<HB / 256, 256>>>(g, c0p, h0p);

        // LSTM1: 64 tiles (h0p 32 | h1prev 32), 4 splits x 16
        k_gemm<32><<<dim3(G4 / 32, 4), 256>>>(
            Wih1, h0p, 1024, 32,
            Whh1, h1prev, 1024, 32,
            nullptr, nullptr, 0, 0,
            16, bih1, bhh1, g, GP);
        k_gates<<<HB / 256, 256>>>(g, c1p, htop);

        // keys[t]: 32 tiles, 4 splits x 8 -> partials
        k_gemm<32><<<dim3(HH / 32, 4), 256>>>(
            Wk, htop, 1024, 32,
            nullptr, nullptr, 0, 0,
            nullptr, nullptr, 0, 0,
            8, bk, nullptr, kp, (long long)HB);
        k_scores<<<t + 1, 256>>>(keys, kp, htop, toks, sc, t);
        k_summary<<<HB / 256, 256>>>(sc, hbuf, t, dist, sumv);

        // comb: 64 tiles (htop 32 | sumv 32), 4 splits x 16 -> partials
        k_gemm<32><<<dim3(HH / 32, 4), 256>>>(
            Wc, htop, 2048, 32,
            Wc + 1024, sumv, 2048, 32,
            nullptr, nullptr, 0, 0,
            16, bc, nullptr, cp, (long long)HB);
        k_fincomb<<<HB / 256, 256>>>(cp, comb);

        // logits: 32 tiles, no split (500 blocks)
        k_gemm<64><<<dim3(VV / 64, 1), 256>>>(
            Wp, comb, 1024, 32,
            nullptr, nullptr, 0, 0,
            nullptr, nullptr, 0, 0,
            32, bp, nullptr, logits, 0);
        k_reduce1<<<125, 256>>>(logits, red);
        k_reduce2<<<1, 32>>>(red, logits, pmax, pinv, cwv);
        k_out<<<250, 256>>>(logits, pmax, pinv, cwv, out, t);
        k_fixup<<<t + 1, BB>>>(toks, dist, logits, pmax, pinv, cwv, out, t);
    }
}